// round 9
// baseline (speedup 1.0000x reference)
#include <cuda_runtime.h>

// loss = max(2 * mean(a @ b.T), 1e-7)
//      = max((2/(N*M)) * dot(colsum(a), colsum(b)), 1e-7)
// One persistent kernel. Latency-bound fix: 8-deep batched independent
// LDG.128 per thread (64 regs), flat float4 indexing, column fixed per thread.

#define TPB   128
#define BPM   592                     // blocks per matrix
#define GRID  (2 * BPM)               // 1184 = 8 CTAs/SM
#define STRD  (BPM * TPB)             // 75776 float4 stride (multiple of 128)
#define LIMIT (16384 * 128)           // 2097152 float4 per matrix
// per-thread iters: 27 always valid (idx0 + 26*STRD < LIMIT for all idx0),
// iteration 27 valid only for idx0 < LIMIT - 27*STRD = 51200.

__device__ float g_colsum[1024];      // [0..511]=colsum(a), [512..1023]=colsum(b)
__device__ unsigned int g_count;      // arrival counter (zero-init; reset each run)

__global__ void __launch_bounds__(TPB, 8) qgc_fused(
    const float* __restrict__ a, const float* __restrict__ b,
    float* __restrict__ out)
{
    __shared__ unsigned s_rank;
    __shared__ double   s_warp[4];

    const int mat = blockIdx.x & 1;
    const int bid = blockIdx.x >> 1;
    const int t   = threadIdx.x;
    const float4* __restrict__ src =
        reinterpret_cast<const float4*>(mat ? b : a);

    const int idx0 = bid * TPB + t;           // 0 .. 75775 ; column = t
    const float4* p = src + idx0;

    float ax = 0.f, ay = 0.f, az = 0.f, aw = 0.f;
    float4 v[8];

    // 3 batches of 8 independent loads (iters 0..23)
    #pragma unroll
    for (int batch = 0; batch < 3; ++batch) {
        #pragma unroll
        for (int j = 0; j < 8; ++j)
            v[j] = __ldcs(p + (size_t)(batch * 8 + j) * STRD);
        #pragma unroll
        for (int j = 0; j < 8; ++j) {
            ax += v[j].x; ay += v[j].y; az += v[j].z; aw += v[j].w;
        }
    }

    // iters 24..26 always valid, iter 27 predicated
    {
        float4 w0 = __ldcs(p + (size_t)24 * STRD);
        float4 w1 = __ldcs(p + (size_t)25 * STRD);
        float4 w2 = __ldcs(p + (size_t)26 * STRD);
        if (idx0 < LIMIT - 27 * STRD) {
            float4 w3 = __ldcs(p + (size_t)27 * STRD);
            ax += w3.x; ay += w3.y; az += w3.z; aw += w3.w;
        }
        ax += w0.x; ay += w0.y; az += w0.z; aw += w0.w;
        ax += w1.x; ay += w1.y; az += w1.z; aw += w1.w;
        ax += w2.x; ay += w2.y; az += w2.z; aw += w2.w;
    }

    // each thread owns a unique float4 column: direct global accumulate
    float* dst = g_colsum + mat * 512 + t * 4;
    atomicAdd(dst + 0, ax);
    atomicAdd(dst + 1, ay);
    atomicAdd(dst + 2, az);
    atomicAdd(dst + 3, aw);
    __threadfence();

    __syncthreads();
    if (t == 0) s_rank = atomicAdd(&g_count, 1u);
    __syncthreads();

    // last-arriving block: fp64 dot, write out, reset scratch
    if (s_rank == GRID - 1) {
        __threadfence();
        double pr = 0.0;
        #pragma unroll
        for (int j = 0; j < 4; ++j) {
            int c = t + j * 128;
            pr += (double)__ldcg(&g_colsum[c]) * (double)__ldcg(&g_colsum[512 + c]);
        }
        #pragma unroll
        for (int o = 16; o > 0; o >>= 1)
            pr += __shfl_down_sync(0xffffffffu, pr, o);
        if ((t & 31) == 0) s_warp[t >> 5] = pr;
        __syncthreads();

        if (t == 0) {
            double v4 = s_warp[0] + s_warp[1] + s_warp[2] + s_warp[3];
            double loss = 2.0 * v4 / ((double)16384 * (double)16384);
            out[0] = (float)(loss < 1e-7 ? 1e-7 : loss);
        }
        __syncthreads();

        // reset for next graph replay
        #pragma unroll
        for (int j = 0; j < 8; ++j)
            g_colsum[t + j * 128] = 0.f;
        if (t == 0) g_count = 0u;
    }
}

extern "C" void kernel_launch(void* const* d_in, const int* in_sizes, int n_in,
                              void* d_out, int out_size) {
    const float* a = (const float*)d_in[0];
    const float* b = (const float*)d_in[1];
    float* out = (float*)d_out;

    qgc_fused<<<GRID, TPB>>>(a, b, out);
}